// round 7
// baseline (speedup 1.0000x reference)
#include <cuda_runtime.h>
#include <math.h>

#define TOLC   0.5f
#define RESC   0.03f
#define GPTS   4000
#define BATCH  128
#define NEV    64
#define HEV    128
#define NTHR   256
#define NQUART 4
#define GSUB   (GPTS / NQUART)     // 1000 grid points per block
#define PER_T  4                   // 250 active threads * 4 = 1000
#define NBLK   (BATCH * NQUART)    // 512

#define LOG2E_F  1.4426950408889634f
#define LN2_F    0.6931471805599453f
#define E_ZERO  (-100000)
#define FXSCALE  1073741824.0      // 2^30

__device__ unsigned long long g_acc = 0ull;
__device__ unsigned int g_cnt = 0;

__device__ __forceinline__ int lower_bound_s(const float* __restrict__ a, int n, float x) {
    int lo = 0, hi = n;
    while (lo < hi) {
        int m = (lo + hi) >> 1;
        if (a[m] < x) lo = m + 1; else hi = m;
    }
    return lo;
}

// (m, e) pair: value = m * 2^e with m in [1,2), or m==0 (zero)
__device__ __forceinline__ void pair_add(float& am, int& ae, float bm, int be) {
    if (bm == 0.f) return;
    if (am == 0.f) { am = bm; ae = be; return; }
    int d = ae - be;
    float m; int e;
    if (d >= 0) { m = am + ldexpf(bm, -d); e = ae; }
    else        { m = bm + ldexpf(am,  d); e = be; }
    if (m >= 2.f) { m *= 0.5f; e += 1; }
    am = m; ae = e;
}

__device__ __forceinline__ float pair_log2(float m, int e) {
    return (m > 0.f) ? ((float)e + __log2f(m)) : -INFINITY;
}

__device__ __forceinline__ void pair_from_log2(float x, float& m, int& e) {
    float n = floorf(x);
    m = exp2f(x - n); e = (int)n;
    if (m >= 2.f) { m *= 0.5f; e += 1; }
}

__device__ __forceinline__ float warp_sum(float v) {
    v += __shfl_down_sync(0xffffffffu, v, 16);
    v += __shfl_down_sync(0xffffffffu, v, 8);
    v += __shfl_down_sync(0xffffffffu, v, 4);
    v += __shfl_down_sync(0xffffffffu, v, 2);
    v += __shfl_down_sync(0xffffffffu, v, 1);
    return v;
}

__global__ __launch_bounds__(NTHR, 4)
void llm_fused_kernel(const float* __restrict__ times0, const int* __restrict__ states0,
                      const float* __restrict__ times1, const int* __restrict__ states1,
                      const float* __restrict__ head_times, const int* __restrict__ head_states,
                      const float* __restrict__ base_p, const float* __restrict__ weights,
                      float* __restrict__ out)
{
    const int b = blockIdx.x >> 2;       // batch
    const int q = blockIdx.x & 3;        // quarter
    const int t = threadIdx.x;
    const int lane = t & 31;
    const int wrp  = t >> 5;

    __shared__ float sh_t0[NEV], sh_t1[NEV], sh_ht[HEV];
    __shared__ int   sh_hs[HEV];
    __shared__ float sh_P0[NEV + 1];
    __shared__ float sh_L0[NEV + 1], sh_L1[NEV + 1];
    __shared__ float wt_m[3]; __shared__ int wt_e[3];
    __shared__ float red[NTHR / 32];

    // ---- warps 2-5 load head arrays while warps 0-1 run the prologue ----
    if (t >= 64 && t < 192) {
        const int j = t - 64;
        sh_ht[j] = head_times[b * HEV + j];
        sh_hs[j] = head_states[b * HEV + j];
    }

    // ================= prologue: warps 0-1 only =================
    if (t < NEV) {
        const int w = wrp;   // 0 or 1
        const float t0j = times0[b * NEV + t];
        const int   s0j = states0[b * NEV + t];
        const float t1j = times1[b * NEV + t];
        const int   s1j = states1[b * NEV + t];
        sh_t0[t] = t0j;
        sh_t1[t] = t1j;

        // A: dual pair-scans of exp(t0_j) masked by s0
        float xa = t0j * LOG2E_F;
        float ma, mb; int ea, eb;
        pair_from_log2(xa, ma, ea);
        mb = ma; eb = ea;
        if (s0j == 1) { mb = 0.f; eb = E_ZERO; }   // b: s0==0 (L1)
        else          { ma = 0.f; ea = E_ZERO; }   // a: s0==1 (P0)

        #pragma unroll
        for (int off = 1; off < 32; off <<= 1) {
            float oma = __shfl_up_sync(0xffffffffu, ma, off);
            int   oea = __shfl_up_sync(0xffffffffu, ea, off);
            float omb = __shfl_up_sync(0xffffffffu, mb, off);
            int   oeb = __shfl_up_sync(0xffffffffu, eb, off);
            if (lane >= off) { pair_add(ma, ea, oma, oea); pair_add(mb, eb, omb, oeb); }
        }
        if (w == 0 && lane == 31) { wt_m[0] = ma; wt_e[0] = ea; wt_m[1] = mb; wt_e[1] = eb; }
        asm volatile("bar.sync 1, 64;" ::: "memory");
        if (w == 1) { pair_add(ma, ea, wt_m[0], wt_e[0]); pair_add(mb, eb, wt_m[1], wt_e[1]); }
        sh_P0[t + 1] = pair_log2(ma, ea);
        sh_L1[t + 1] = pair_log2(mb, eb);
        if (t == 0) { sh_P0[0] = -INFINITY; sh_L1[0] = -INFINITY; sh_L0[0] = -INFINITY; }
        asm volatile("bar.sync 1, 64;" ::: "memory");

        // B: ps0_j = exp(t1_j) * P0[c_j]
        float m0 = 0.f; int e0 = E_ZERO;
        if (s1j == 1) {
            const int cj = lower_bound_s(sh_t0, NEV, t1j - TOLC);
            const float p = sh_P0[cj];
            if (p > -INFINITY) pair_from_log2(t1j * LOG2E_F + p, m0, e0);
        }
        // C: pair-scan -> L0
        #pragma unroll
        for (int off = 1; off < 32; off <<= 1) {
            float om0 = __shfl_up_sync(0xffffffffu, m0, off);
            int   oe0 = __shfl_up_sync(0xffffffffu, e0, off);
            if (lane >= off) pair_add(m0, e0, om0, oe0);
        }
        if (w == 0 && lane == 31) { wt_m[2] = m0; wt_e[2] = e0; }
        asm volatile("bar.sync 1, 64;" ::: "memory");
        if (w == 1) pair_add(m0, e0, wt_m[2], wt_e[2]);
        sh_L0[t + 1] = pair_log2(m0, e0);
    }
    __syncthreads();

    // ---- softmax(weights), base ----
    const float w0 = weights[0], w1 = weights[1];
    const float mw = fmaxf(w0, w1);
    const float ew0 = __expf(w0 - mw), ew1 = __expf(w1 - mw);
    const float inv = 1.f / (ew0 + ew1);
    const float wn0 = ew0 * inv, wn1 = ew1 * inv;
    const float base = base_p[0];

    // ================= grid evaluation: this block's quarter ===============
    float lamsum = 0.f;
    const int gbeg = q * GSUB + t * PER_T;
    if (t * PER_T < GSUB) {
        float te  = (float)gbeg * RESC;
        float thr = te - TOLC;
        int c   = lower_bound_s(sh_t1, NEV, thr);
        int c1  = lower_bound_s(sh_t0, NEV, thr);
        int cnt = lower_bound_s(sh_ht, HEV, te);
        float nt1 = (c   < NEV) ? sh_t1[c]   : 1e30f;
        float nt0 = (c1  < NEV) ? sh_t0[c1]  : 1e30f;
        float nht = (cnt < HEV) ? sh_ht[cnt] : 1e30f;
        float f0  = __expf(fmaf(LN2_F, sh_L0[c],  -2.f * te));
        float f1  = __expf(fmaf(LN2_F, sh_L1[c1], -te));
        float eff0 = (sh_hs[(cnt + HEV - 1) & (HEV - 1)] == 0) ? 1.f : -1.f;
        const float d2 = 0.886920437f;   // exp(-2*RES)
        const float d1 = 0.970445527f;   // exp(-RES)

        #pragma unroll
        for (int g = gbeg; g < gbeg + PER_T; ++g) {
            if (g > gbeg) {
                te  = (float)g * RESC;
                thr = te - TOLC;
                f0 *= d2;
                f1 *= d1;
                if (nt1 < thr || nt0 < thr || nht < te) {   // single rare slow path
                    while (nt1 < thr) { c++;  nt1 = (c  < NEV) ? sh_t1[c]  : 1e30f; }
                    while (nt0 < thr) { c1++; nt0 = (c1 < NEV) ? sh_t0[c1] : 1e30f; }
                    while (nht < te)  { cnt++; nht = (cnt < HEV) ? sh_ht[cnt] : 1e30f; }
                    f0 = __expf(fmaf(LN2_F, sh_L0[c],  -2.f * te));
                    f1 = __expf(fmaf(LN2_F, sh_L1[c1], -te));
                    eff0 = (sh_hs[(cnt + HEV - 1) & (HEV - 1)] == 0) ? 1.f : -1.f;
                }
            }
            lamsum += __expf(base + eff0 * (wn0 * f0 - wn1 * f1));
        }
    }

    // ---- event points: this block handles events [q*32, q*32+32) \ {0} ----
    float logsum = 0.f;
    if (t < 32) {
        const int ev = q * 32 + t;
        if (ev >= 1) {
            const float te  = sh_ht[ev];
            const float thr = te - TOLC;
            const int c   = lower_bound_s(sh_t1, NEV, thr);
            const int c1  = lower_bound_s(sh_t0, NEV, thr);
            const float feat0 = __expf(fmaf(LN2_F, sh_L0[c],  -2.f * te));
            const float feat1 = __expf(fmaf(LN2_F, sh_L1[c1], -te));
            const float eff0  = (sh_hs[ev - 1] == 0) ? 1.f : -1.f;   // cnt(ht[ev]) == ev
            logsum = base + eff0 * (wn0 * feat0 - wn1 * feat1);
        }
    }

    // ================= reduce: block -> fixed-point global atomic =========
    float pv = warp_sum(logsum - RESC * lamsum);
    if (lane == 0) red[wrp] = pv;
    __syncthreads();
    if (t < 32) {
        float s = (t < NTHR / 32) ? red[t] : 0.f;
        s = warp_sum(s);
        if (t == 0) {
            long long iq = llrint((double)s * FXSCALE);
            atomicAdd(&g_acc, (unsigned long long)iq);
            __threadfence();
            unsigned int prev = atomicAdd(&g_cnt, 1u);
            if (prev == (unsigned int)(NBLK - 1)) {
                unsigned long long tot = atomicAdd(&g_acc, 0ull);
                out[0] = (float)((double)(long long)tot * (1.0 / FXSCALE));
                g_acc = 0ull;     // reset for next graph replay
                g_cnt = 0u;
            }
        }
    }
}

extern "C" void kernel_launch(void* const* d_in, const int* in_sizes, int n_in,
                              void* d_out, int out_size)
{
    const float* times0      = (const float*)d_in[0];
    const int*   states0     = (const int*)  d_in[1];
    const float* times1      = (const float*)d_in[2];
    const int*   states1     = (const int*)  d_in[3];
    const float* head_times  = (const float*)d_in[4];
    const int*   head_states = (const int*)  d_in[5];
    const float* base_p      = (const float*)d_in[6];
    const float* weights     = (const float*)d_in[7];
    float* out = (float*)d_out;

    llm_fused_kernel<<<NBLK, NTHR>>>(times0, states0, times1, states1,
                                     head_times, head_states, base_p, weights, out);
}